// round 6
// baseline (speedup 1.0000x reference)
#include <cuda_runtime.h>
#include <cuda_bf16.h>

// Problem constants (fixed dataset): N=50000, E=800000, IN_F=256, OUT_F=64, HEADS=8
#define IN_F 256
#define OUT_F 64
#define MAXN 50000
#define MAXE 800000

// Static device scratch (no allocation allowed)
__device__ float g_hp[MAXN * OUT_F];      // projected features [N, 64]
__device__ int   g_counts[MAXN];          // in-degree histogram (invariant: 0 on entry)
__device__ int   g_offsets[MAXN + 1];     // CSR offsets by dst
__device__ int   g_cursors[MAXN];         // scatter cursors
__device__ int   g_esrc[MAXE];            // src node id per edge, bucketed by dst

// Multi-block scan config
#define SCAN_T 256
#define SCAN_E 4
#define SCAN_CHUNK (SCAN_T * SCAN_E)                       // 1024 elems / block
#define SCAN_B ((MAXN + SCAN_CHUNK - 1) / SCAN_CHUNK)      // 49 blocks
__device__ int g_bsum[SCAN_B + 1];

// Packed fp32x2 helpers (Blackwell sm_100+; ptxas will not auto-fuse these)
#define FMA_F32X2(d, a, b, c) \
    asm("fma.rn.f32x2 %0, %1, %2, %3;" : "=l"(d) : "l"(a), "l"(b), "l"(c))
#define UNPACK2(lo, hi, in) \
    asm("mov.b64 {%0, %1}, %2;" : "=f"(lo), "=f"(hi) : "l"(in))

// ---------------------------------------------------------------------------
// K1: histogram of dst (counts are zero on entry — re-zeroed by scan_add)
// ---------------------------------------------------------------------------
__global__ void hist_kernel(const int* __restrict__ dst, int e) {
    int i4 = (blockIdx.x * blockDim.x + threadIdx.x) * 4;
    if (i4 + 3 < e) {
        int4 d = *(const int4*)&dst[i4];
        atomicAdd(&g_counts[d.x], 1);
        atomicAdd(&g_counts[d.y], 1);
        atomicAdd(&g_counts[d.z], 1);
        atomicAdd(&g_counts[d.w], 1);
    } else {
        for (int i = i4; i < e; i++) atomicAdd(&g_counts[dst[i]], 1);
    }
}

// ---------------------------------------------------------------------------
// K2a: block-local exclusive scan of counts.
// ---------------------------------------------------------------------------
__global__ __launch_bounds__(SCAN_T)
void scan_local_kernel(int n) {
    __shared__ int warp_sums[SCAN_T / 32];
    int t    = threadIdx.x;
    int base = blockIdx.x * SCAN_CHUNK + t * SCAN_E;

    int v[SCAN_E];
#pragma unroll
    for (int i = 0; i < SCAN_E; i++)
        v[i] = (base + i < n) ? g_counts[base + i] : 0;

    int tsum = 0;
#pragma unroll
    for (int i = 0; i < SCAN_E; i++) tsum += v[i];

    int lane = t & 31, wid = t >> 5;
    int incl = tsum;
#pragma unroll
    for (int o = 1; o < 32; o <<= 1) {
        int x = __shfl_up_sync(0xFFFFFFFFu, incl, o);
        if (lane >= o) incl += x;
    }
    if (lane == 31) warp_sums[wid] = incl;
    __syncthreads();
    if (wid == 0) {
        int s = (lane < SCAN_T / 32) ? warp_sums[lane] : 0;
#pragma unroll
        for (int o = 1; o < SCAN_T / 32; o <<= 1) {
            int x = __shfl_up_sync(0xFFFFFFFFu, s, o);
            if (lane >= o) s += x;
        }
        if (lane < SCAN_T / 32) warp_sums[lane] = s;
    }
    __syncthreads();

    int texcl = (incl - tsum) + (wid > 0 ? warp_sums[wid - 1] : 0);

    int run = texcl;
#pragma unroll
    for (int i = 0; i < SCAN_E; i++) {
        if (base + i < n) g_offsets[base + i] = run;
        run += v[i];
    }
    if (t == SCAN_T - 1) g_bsum[blockIdx.x] = warp_sums[SCAN_T / 32 - 1];
}

// ---------------------------------------------------------------------------
// K2b: spine scan (SCAN_B=49 values) in one small block.
// ---------------------------------------------------------------------------
__global__ __launch_bounds__(64)
void scan_spine_kernel() {
    __shared__ int sm[64];
    int t = threadIdx.x;
    int v = (t < SCAN_B) ? g_bsum[t] : 0;
    sm[t] = v;
    __syncthreads();
    int incl = v;
#pragma unroll
    for (int o = 1; o < 64; o <<= 1) {
        int add = (t >= o) ? sm[t - o] : 0;
        __syncthreads();
        incl += add;
        sm[t] = incl;
        __syncthreads();
    }
    if (t < SCAN_B) g_bsum[t] = incl - v;     // exclusive
    if (t == 63)    g_bsum[SCAN_B] = sm[63];  // total
}

// ---------------------------------------------------------------------------
// K2c: add spine base, finalize offsets + cursors, re-zero counts, sentinel.
// ---------------------------------------------------------------------------
__global__ __launch_bounds__(SCAN_T)
void scan_add_kernel(int n) {
    int b    = blockIdx.x;
    int boff = g_bsum[b];
    int base = b * SCAN_CHUNK + threadIdx.x * SCAN_E;
#pragma unroll
    for (int i = 0; i < SCAN_E; i++) {
        int idx = base + i;
        if (idx < n) {
            int o = g_offsets[idx] + boff;
            g_offsets[idx] = o;
            g_cursors[idx] = o;
            g_counts[idx] = 0;            // restore invariant for next call
        }
    }
    if (b == 0 && threadIdx.x == 0) g_offsets[n] = g_bsum[SCAN_B];
}

// ---------------------------------------------------------------------------
// K3: scatter edges into CSR buckets by dst (standalone, full occupancy)
// ---------------------------------------------------------------------------
__global__ void scatter_kernel(const int* __restrict__ src,
                               const int* __restrict__ dst, int e) {
    int i = blockIdx.x * blockDim.x + threadIdx.x;
    if (i < e) {
        int p = atomicAdd(&g_cursors[dst[i]], 1);
        g_esrc[p] = src[i];
    }
}

// ---------------------------------------------------------------------------
// K4: GEMM hp = h @ W. 32-row x 64-col tile, 128 threads, 4 rows x 4 cols per
// thread. h is stored DUPLICATED in smem ((v,v) pairs) so one LDS.64 yields a
// packed f32x2 broadcast operand directly — no pack movs in the inner loop.
// Dynamic smem: 32 rows * 520 floats * 4B = 66560 bytes.
// ---------------------------------------------------------------------------
#define G_ROWS 32
#define G_THREADS 128
#define G_PITCH2 520   // 2*IN_F + 8 pad (keeps 8B/16B alignment per row)
#define G_SMEM_BYTES (G_ROWS * G_PITCH2 * 4)

__global__ __launch_bounds__(G_THREADS)
void gemm_kernel(const float* __restrict__ h, const float* __restrict__ W, int n) {
    extern __shared__ float sh[];

    int block_row = blockIdx.x * G_ROWS;

    // Fill duplicated tile: for each h float4 (r, c4) write (x,x,y,y) and (z,z,w,w)
    for (int i = threadIdx.x; i < G_ROWS * (IN_F / 4); i += G_THREADS) {
        int r  = i / (IN_F / 4);
        int c4 = (i % (IN_F / 4)) * 4;
        float4 v = make_float4(0.f, 0.f, 0.f, 0.f);
        int gr = block_row + r;
        if (gr < n) v = *(const float4*)&h[(size_t)gr * IN_F + c4];
        float* dstp = &sh[r * G_PITCH2 + 2 * c4];
        *(float4*)(dstp)     = make_float4(v.x, v.x, v.y, v.y);
        *(float4*)(dstp + 4) = make_float4(v.z, v.z, v.w, v.w);
    }
    __syncthreads();

    int tx = threadIdx.x & 15;   // col group (16 groups of 4 cols)
    int ty = threadIdx.x >> 4;   // row group (8 groups of 4 rows)
    int col  = tx * 4;
    int row0 = ty * 4;

    unsigned long long acc2[4][2];
#pragma unroll
    for (int i = 0; i < 4; i++) { acc2[i][0] = 0ULL; acc2[i][1] = 0ULL; }

#pragma unroll 4
    for (int k = 0; k < IN_F; k++) {
        ulonglong2 wv = *(const ulonglong2*)&W[k * OUT_F + col];
#pragma unroll
        for (int i = 0; i < 4; i++) {
            unsigned long long hv2 =
                *(const unsigned long long*)&sh[(row0 + i) * G_PITCH2 + 2 * k];
            FMA_F32X2(acc2[i][0], hv2, wv.x, acc2[i][0]);
            FMA_F32X2(acc2[i][1], hv2, wv.y, acc2[i][1]);
        }
    }

#pragma unroll
    for (int i = 0; i < 4; i++) {
        int gr = block_row + row0 + i;
        if (gr < n) {
            float4 o;
            UNPACK2(o.x, o.y, acc2[i][0]);
            UNPACK2(o.z, o.w, acc2[i][1]);
            *(float4*)&g_hp[(size_t)gr * OUT_F + col] = o;
        }
    }
}

// ---------------------------------------------------------------------------
// K5: aggregation, 8 lanes per edge / 4 edges per warp iteration.
// lane = grp*8 + sub: grp = edge slot (0..3), sub = feature octet (0..7).
// Each lane owns features [sub*8, sub*8+8) as 2 float4.
// Per iteration: group dot via 3 shfl; acc += dot * x. Cross-group merge once
// at the end (xor 8, 16). Invalid slots force dot=0 (garbage x contributes 0).
// ---------------------------------------------------------------------------
__global__ __launch_bounds__(256)
void aggregate_kernel(const float* __restrict__ aw, int n_aw,
                      float* __restrict__ out, int n) {
    int warp = (blockIdx.x * blockDim.x + threadIdx.x) >> 5;
    int lane = threadIdx.x & 31;
    if (warp >= n) return;

    float c = 0.f;
    for (int i = 0; i < n_aw; i++) c += __ldg(&aw[i]);

    int sub = lane & 7;
    int grp = lane >> 3;

    const float4* __restrict__ hp4 = (const float4*)g_hp;   // [n][16]
    int hbase = warp * 16 + sub * 2;
    float4 hd0 = hp4[hbase];
    float4 hd1 = hp4[hbase + 1];

    int beg = g_offsets[warp];
    int fin = g_offsets[warp + 1];

    float acc[8];
#pragma unroll
    for (int j = 0; j < 8; j++) acc[j] = 0.f;

    for (int it = beg; it < fin; it += 4) {
        int id = it + grp;
        bool valid = id < fin;
        int s = valid ? g_esrc[id] : 0;
        int xb = s * 16 + sub * 2;
        float4 x0 = hp4[xb];
        float4 x1 = hp4[xb + 1];

        float p;
        p = x0.x * hd0.x;
        p = fmaf(x0.y, hd0.y, p);
        p = fmaf(x0.z, hd0.z, p);
        p = fmaf(x0.w, hd0.w, p);
        p = fmaf(x1.x, hd1.x, p);
        p = fmaf(x1.y, hd1.y, p);
        p = fmaf(x1.z, hd1.z, p);
        p = fmaf(x1.w, hd1.w, p);
        if (!valid) p = 0.f;

        p += __shfl_xor_sync(0xFFFFFFFFu, p, 1);
        p += __shfl_xor_sync(0xFFFFFFFFu, p, 2);
        p += __shfl_xor_sync(0xFFFFFFFFu, p, 4);

        acc[0] = fmaf(p, x0.x, acc[0]);
        acc[1] = fmaf(p, x0.y, acc[1]);
        acc[2] = fmaf(p, x0.z, acc[2]);
        acc[3] = fmaf(p, x0.w, acc[3]);
        acc[4] = fmaf(p, x1.x, acc[4]);
        acc[5] = fmaf(p, x1.y, acc[5]);
        acc[6] = fmaf(p, x1.z, acc[6]);
        acc[7] = fmaf(p, x1.w, acc[7]);
    }

    // merge the 4 edge-groups (lanes sharing `sub`)
#pragma unroll
    for (int j = 0; j < 8; j++) {
        acc[j] += __shfl_xor_sync(0xFFFFFFFFu, acc[j], 8);
        acc[j] += __shfl_xor_sync(0xFFFFFFFFu, acc[j], 16);
    }

    if (lane < 8) {
        float4* out4 = (float4*)out;
        int ob = warp * 16 + sub * 2;
        if (fin > beg) {
            out4[ob]     = make_float4(c * acc[0], c * acc[1], c * acc[2], c * acc[3]);
            out4[ob + 1] = make_float4(c * acc[4], c * acc[5], c * acc[6], c * acc[7]);
        } else {
            out4[ob]     = hd0;
            out4[ob + 1] = hd1;
        }
    }
}

// ---------------------------------------------------------------------------
extern "C" void kernel_launch(void* const* d_in, const int* in_sizes, int n_in,
                              void* d_out, int out_size) {
    const float* h   = (const float*)d_in[0];
    const float* W   = (const float*)d_in[1];
    const float* aw  = (const float*)d_in[2];
    const int*   src = (const int*)d_in[3];
    const int*   dst = (const int*)d_in[4];
    float* out = (float*)d_out;

    int n    = in_sizes[0] / IN_F;   // 50000
    int e    = in_sizes[3];          // 800000
    int n_aw = in_sizes[2];          // 8

    static bool attr_set = false;
    if (!attr_set) {
        cudaFuncSetAttribute(gemm_kernel,
                             cudaFuncAttributeMaxDynamicSharedMemorySize,
                             G_SMEM_BYTES);
        attr_set = true;
    }

    int gemm_blocks = (n + G_ROWS - 1) / G_ROWS;

    hist_kernel<<<(e / 4 + 255) / 256, 256>>>(dst, e);
    scan_local_kernel<<<SCAN_B, SCAN_T>>>(n);
    scan_spine_kernel<<<1, 64>>>();
    scan_add_kernel<<<SCAN_B, SCAN_T>>>(n);
    scatter_kernel<<<(e + 255) / 256, 256>>>(src, dst, e);
    gemm_kernel<<<gemm_blocks, G_THREADS, G_SMEM_BYTES>>>(h, W, n);
    aggregate_kernel<<<((n * 32) + 255) / 256, 256>>>(aw, n_aw, out, n);
}

// round 7
// speedup vs baseline: 1.5801x; 1.5801x over previous
#include <cuda_runtime.h>
#include <cuda_bf16.h>

// Problem constants (fixed dataset): N=50000, E=800000, IN_F=256, OUT_F=64, HEADS=8
#define IN_F 256
#define OUT_F 64
#define MAXN 50000
#define MAXE 800000

// Static device scratch (no allocation allowed)
__device__ float g_hp[MAXN * OUT_F];      // projected features [N, 64]
__device__ int   g_counts[MAXN];          // in-degree histogram (invariant: 0 on entry)
__device__ int   g_offsets[MAXN + 1];     // CSR offsets by dst
__device__ int   g_cursors[MAXN];         // scatter cursors
__device__ int   g_esrc[MAXE];            // src node id per edge, bucketed by dst

// Multi-block scan config
#define SCAN_T 256
#define SCAN_E 4
#define SCAN_CHUNK (SCAN_T * SCAN_E)                       // 1024 elems / block
#define SCAN_B ((MAXN + SCAN_CHUNK - 1) / SCAN_CHUNK)      // 49 blocks
__device__ int g_bsum[SCAN_B + 1];

// Packed fp32x2 helpers (Blackwell sm_100+)
#define FMA_F32X2(d, a, b, c) \
    asm("fma.rn.f32x2 %0, %1, %2, %3;" : "=l"(d) : "l"(a), "l"(b), "l"(c))
#define PACK2(out, lo, hi) \
    asm("mov.b64 %0, {%1, %2};" : "=l"(out) : "f"(lo), "f"(hi))
#define UNPACK2(lo, hi, in) \
    asm("mov.b64 {%0, %1}, %2;" : "=f"(lo), "=f"(hi) : "l"(in))

// ---------------------------------------------------------------------------
// K1: histogram of dst (counts are zero on entry — re-zeroed by scan_add)
// ---------------------------------------------------------------------------
__global__ void hist_kernel(const int* __restrict__ dst, int e) {
    int i4 = (blockIdx.x * blockDim.x + threadIdx.x) * 4;
    if (i4 + 3 < e) {
        int4 d = *(const int4*)&dst[i4];
        atomicAdd(&g_counts[d.x], 1);
        atomicAdd(&g_counts[d.y], 1);
        atomicAdd(&g_counts[d.z], 1);
        atomicAdd(&g_counts[d.w], 1);
    } else {
        for (int i = i4; i < e; i++) atomicAdd(&g_counts[dst[i]], 1);
    }
}

// ---------------------------------------------------------------------------
// K2a: block-local exclusive scan of counts.
// ---------------------------------------------------------------------------
__global__ __launch_bounds__(SCAN_T)
void scan_local_kernel(int n) {
    __shared__ int warp_sums[SCAN_T / 32];
    int t    = threadIdx.x;
    int base = blockIdx.x * SCAN_CHUNK + t * SCAN_E;

    int v[SCAN_E];
#pragma unroll
    for (int i = 0; i < SCAN_E; i++)
        v[i] = (base + i < n) ? g_counts[base + i] : 0;

    int tsum = 0;
#pragma unroll
    for (int i = 0; i < SCAN_E; i++) tsum += v[i];

    int lane = t & 31, wid = t >> 5;
    int incl = tsum;
#pragma unroll
    for (int o = 1; o < 32; o <<= 1) {
        int x = __shfl_up_sync(0xFFFFFFFFu, incl, o);
        if (lane >= o) incl += x;
    }
    if (lane == 31) warp_sums[wid] = incl;
    __syncthreads();
    if (wid == 0) {
        int s = (lane < SCAN_T / 32) ? warp_sums[lane] : 0;
#pragma unroll
        for (int o = 1; o < SCAN_T / 32; o <<= 1) {
            int x = __shfl_up_sync(0xFFFFFFFFu, s, o);
            if (lane >= o) s += x;
        }
        if (lane < SCAN_T / 32) warp_sums[lane] = s;
    }
    __syncthreads();

    int texcl = (incl - tsum) + (wid > 0 ? warp_sums[wid - 1] : 0);

    int run = texcl;
#pragma unroll
    for (int i = 0; i < SCAN_E; i++) {
        if (base + i < n) g_offsets[base + i] = run;
        run += v[i];
    }
    if (t == SCAN_T - 1) g_bsum[blockIdx.x] = warp_sums[SCAN_T / 32 - 1];
}

// ---------------------------------------------------------------------------
// K2b: spine scan (SCAN_B=49 values) in one small block.
// ---------------------------------------------------------------------------
__global__ __launch_bounds__(64)
void scan_spine_kernel() {
    __shared__ int sm[64];
    int t = threadIdx.x;
    int v = (t < SCAN_B) ? g_bsum[t] : 0;
    sm[t] = v;
    __syncthreads();
    int incl = v;
#pragma unroll
    for (int o = 1; o < 64; o <<= 1) {
        int add = (t >= o) ? sm[t - o] : 0;
        __syncthreads();
        incl += add;
        sm[t] = incl;
        __syncthreads();
    }
    if (t < SCAN_B) g_bsum[t] = incl - v;     // exclusive
    if (t == 63)    g_bsum[SCAN_B] = sm[63];  // total
}

// ---------------------------------------------------------------------------
// K2c: add spine base, finalize offsets + cursors, re-zero counts, sentinel.
// ---------------------------------------------------------------------------
__global__ __launch_bounds__(SCAN_T)
void scan_add_kernel(int n) {
    int b    = blockIdx.x;
    int boff = g_bsum[b];
    int base = b * SCAN_CHUNK + threadIdx.x * SCAN_E;
#pragma unroll
    for (int i = 0; i < SCAN_E; i++) {
        int idx = base + i;
        if (idx < n) {
            int o = g_offsets[idx] + boff;
            g_offsets[idx] = o;
            g_cursors[idx] = o;
            g_counts[idx] = 0;            // restore invariant for next call
        }
    }
    if (b == 0 && threadIdx.x == 0) g_offsets[n] = g_bsum[SCAN_B];
}

// ---------------------------------------------------------------------------
// K3: scatter edges into CSR buckets by dst (standalone, full occupancy)
// ---------------------------------------------------------------------------
__global__ void scatter_kernel(const int* __restrict__ src,
                               const int* __restrict__ dst, int e) {
    int i = blockIdx.x * blockDim.x + threadIdx.x;
    if (i < e) {
        int p = atomicAdd(&g_cursors[dst[i]], 1);
        g_esrc[p] = src[i];
    }
}

// ---------------------------------------------------------------------------
// K4: GEMM hp = h @ W (R3-proven version: 32x64 tile, 128 thr, 4x4/thread,
// f32x2 FMA with per-k hv pack; 33 KB static smem -> high occupancy).
// ---------------------------------------------------------------------------
#define G_ROWS 32
#define G_THREADS 128
#define G_PITCH (IN_F + 4)

__global__ __launch_bounds__(G_THREADS)
void gemm_kernel(const float* __restrict__ h, const float* __restrict__ W, int n) {
    __shared__ float sh[G_ROWS * G_PITCH];

    int block_row = blockIdx.x * G_ROWS;

    for (int i = threadIdx.x; i < G_ROWS * (IN_F / 4); i += G_THREADS) {
        int r  = i / (IN_F / 4);
        int c4 = (i % (IN_F / 4)) * 4;
        float4 v = make_float4(0.f, 0.f, 0.f, 0.f);
        int gr = block_row + r;
        if (gr < n) v = *(const float4*)&h[(size_t)gr * IN_F + c4];
        *(float4*)&sh[r * G_PITCH + c4] = v;
    }
    __syncthreads();

    int tx = threadIdx.x & 15;   // col group (16 groups of 4 cols)
    int ty = threadIdx.x >> 4;   // row group (8 groups of 4 rows)
    int col  = tx * 4;
    int row0 = ty * 4;

    unsigned long long acc2[4][2];
#pragma unroll
    for (int i = 0; i < 4; i++) { acc2[i][0] = 0ULL; acc2[i][1] = 0ULL; }

#pragma unroll 4
    for (int k = 0; k < IN_F; k++) {
        ulonglong2 wv = *(const ulonglong2*)&W[k * OUT_F + col];
#pragma unroll
        for (int i = 0; i < 4; i++) {
            float hv = sh[(row0 + i) * G_PITCH + k];
            unsigned long long hv2;
            PACK2(hv2, hv, hv);
            FMA_F32X2(acc2[i][0], hv2, wv.x, acc2[i][0]);
            FMA_F32X2(acc2[i][1], hv2, wv.y, acc2[i][1]);
        }
    }

#pragma unroll
    for (int i = 0; i < 4; i++) {
        int gr = block_row + row0 + i;
        if (gr < n) {
            float4 o;
            UNPACK2(o.x, o.y, acc2[i][0]);
            UNPACK2(o.z, o.w, acc2[i][1]);
            *(float4*)&g_hp[(size_t)gr * OUT_F + col] = o;
        }
    }
}

// ---------------------------------------------------------------------------
// K5: warp-per-destination-node aggregation (float2 lanes, R4/R5-proven).
// out[n] = (deg>0) ? c * sum_{e: dst=n} dot(hs,hd)*hs  :  hp[n]
// ---------------------------------------------------------------------------
__global__ __launch_bounds__(256)
void aggregate_kernel(const float* __restrict__ aw, int n_aw,
                      float* __restrict__ out, int n) {
    int warp = (blockIdx.x * blockDim.x + threadIdx.x) >> 5;
    int lane = threadIdx.x & 31;
    if (warp >= n) return;

    float c = 0.f;
    for (int i = 0; i < n_aw; i++) c += __ldg(&aw[i]);

    const float2* __restrict__ hp2 = (const float2*)g_hp;   // [n][32] float2
    float2 hd = hp2[warp * 32 + lane];

    int beg = g_offsets[warp];
    int fin = g_offsets[warp + 1];

    float a0 = 0.f, a1 = 0.f;
    int e = beg;
    for (; e + 1 < fin; e += 2) {
        int s0 = g_esrc[e];
        int s1 = g_esrc[e + 1];
        float2 x = hp2[(size_t)s0 * 32 + lane];
        float2 y = hp2[(size_t)s1 * 32 + lane];
        float p = fmaf(x.x, hd.x, x.y * hd.y);
        float q = fmaf(y.x, hd.x, y.y * hd.y);
#pragma unroll
        for (int o = 16; o > 0; o >>= 1) {
            p += __shfl_xor_sync(0xFFFFFFFFu, p, o);
            q += __shfl_xor_sync(0xFFFFFFFFu, q, o);
        }
        a0 = fmaf(p, x.x, a0);
        a1 = fmaf(p, x.y, a1);
        a0 = fmaf(q, y.x, a0);
        a1 = fmaf(q, y.y, a1);
    }
    if (e < fin) {
        int s0 = g_esrc[e];
        float2 x = hp2[(size_t)s0 * 32 + lane];
        float p = fmaf(x.x, hd.x, x.y * hd.y);
#pragma unroll
        for (int o = 16; o > 0; o >>= 1)
            p += __shfl_xor_sync(0xFFFFFFFFu, p, o);
        a0 = fmaf(p, x.x, a0);
        a1 = fmaf(p, x.y, a1);
    }

    float2* out2 = (float2*)out;
    if (fin > beg) {
        out2[warp * 32 + lane] = make_float2(c * a0, c * a1);
    } else {
        out2[warp * 32 + lane] = hd;
    }
}

// ---------------------------------------------------------------------------
// Fork/join: GEMM runs on the capture stream while the CSR-build chain
// (hist -> scan x3 -> scatter) runs on a side stream. aggregate joins both.
// ---------------------------------------------------------------------------
extern "C" void kernel_launch(void* const* d_in, const int* in_sizes, int n_in,
                              void* d_out, int out_size) {
    const float* h   = (const float*)d_in[0];
    const float* W   = (const float*)d_in[1];
    const float* aw  = (const float*)d_in[2];
    const int*   src = (const int*)d_in[3];
    const int*   dst = (const int*)d_in[4];
    float* out = (float*)d_out;

    int n    = in_sizes[0] / IN_F;   // 50000
    int e    = in_sizes[3];          // 800000
    int n_aw = in_sizes[2];          // 8

    static cudaStream_t s2 = nullptr;
    static cudaEvent_t evFork = nullptr, evJoin = nullptr;
    if (s2 == nullptr) {
        cudaStreamCreateWithFlags(&s2, cudaStreamNonBlocking);
        cudaEventCreateWithFlags(&evFork, cudaEventDisableTiming);
        cudaEventCreateWithFlags(&evJoin, cudaEventDisableTiming);
    }

    int gemm_blocks = (n + G_ROWS - 1) / G_ROWS;

    // Fork: side stream joins the capture at this point
    cudaEventRecord(evFork, 0);
    cudaStreamWaitEvent(s2, evFork, 0);

    // Branch B (side stream): CSR build
    hist_kernel<<<(e / 4 + 255) / 256, 256, 0, s2>>>(dst, e);
    scan_local_kernel<<<SCAN_B, SCAN_T, 0, s2>>>(n);
    scan_spine_kernel<<<1, 64, 0, s2>>>();
    scan_add_kernel<<<SCAN_B, SCAN_T, 0, s2>>>(n);
    scatter_kernel<<<(e + 255) / 256, 256, 0, s2>>>(src, dst, e);
    cudaEventRecord(evJoin, s2);

    // Branch A (capture stream): GEMM
    gemm_kernel<<<gemm_blocks, G_THREADS>>>(h, W, n);

    // Join, then aggregate
    cudaStreamWaitEvent(0, evJoin, 0);
    aggregate_kernel<<<((n * 32) + 255) / 256, 256>>>(aw, n_aw, out, n);
}